// round 3
// baseline (speedup 1.0000x reference)
#include <cuda_runtime.h>

// SWT Haar level-1 MSE loss reduces analytically to plain MSE:
//   loss = mean((x - target)^2)
// Proof: with d = x - t, per-position coeff-diff energy is
//   ((d[i]+d[i+1])^2 + (d[i+1]-d[i])^2)/2 = d[i]^2 + d[i+1]^2,
// circular (periodic) sum = 2*sum(d^2); mean over the 2N stacked
// (cA, cD) coefficients = sum(d^2)/N = MSE(x, target).
//
// N = 16*3*512*512 = 12,582,912 floats per input (divisible by 16).
//
// Single-kernel deterministic reduction: per-block double partials in
// __device__ scratch; the last block (by atomic ticket) sums all partials
// in fixed order and writes the result, then resets the ticket so every
// graph replay starts from identical state.

#define NBLOCKS 1184
#define NTHREADS 256
#define UNROLL 4

__device__ double g_partials[NBLOCKS];
__device__ unsigned int g_ticket = 0;   // always 0 between launches

__global__ void __launch_bounds__(NTHREADS)
swt_mse_kernel(const float4* __restrict__ x,
               const float4* __restrict__ t,
               int n4, float* __restrict__ out, double inv_n) {
    const int tid    = blockIdx.x * NTHREADS + threadIdx.x;
    const int stride = NBLOCKS * NTHREADS;

    float acc0 = 0.0f, acc1 = 0.0f, acc2 = 0.0f, acc3 = 0.0f;

    // Main unrolled loop: 8 independent LDG.128 front-batched per trip
    // (MLP_p1 = 8) -> DRAM latency fully overlapped.
    int i = tid;
    const int bound = n4 - (UNROLL - 1) * stride;
    for (; i < bound; i += UNROLL * stride) {
        float4 a0 = x[i];
        float4 a1 = x[i + stride];
        float4 a2 = x[i + 2 * stride];
        float4 a3 = x[i + 3 * stride];
        float4 b0 = t[i];
        float4 b1 = t[i + stride];
        float4 b2 = t[i + 2 * stride];
        float4 b3 = t[i + 3 * stride];

        float d;
        d = a0.x - b0.x; acc0 += d * d;
        d = a0.y - b0.y; acc0 += d * d;
        d = a0.z - b0.z; acc0 += d * d;
        d = a0.w - b0.w; acc0 += d * d;
        d = a1.x - b1.x; acc1 += d * d;
        d = a1.y - b1.y; acc1 += d * d;
        d = a1.z - b1.z; acc1 += d * d;
        d = a1.w - b1.w; acc1 += d * d;
        d = a2.x - b2.x; acc2 += d * d;
        d = a2.y - b2.y; acc2 += d * d;
        d = a2.z - b2.z; acc2 += d * d;
        d = a2.w - b2.w; acc2 += d * d;
        d = a3.x - b3.x; acc3 += d * d;
        d = a3.y - b3.y; acc3 += d * d;
        d = a3.z - b3.z; acc3 += d * d;
        d = a3.w - b3.w; acc3 += d * d;
    }
    // Tail: remaining grid-stride trips
    for (; i < n4; i += stride) {
        float4 a = x[i];
        float4 b = t[i];
        float d;
        d = a.x - b.x; acc0 += d * d;
        d = a.y - b.y; acc1 += d * d;
        d = a.z - b.z; acc2 += d * d;
        d = a.w - b.w; acc3 += d * d;
    }

    // Block reduction (double from here: 12.6M-term sum, and it's free —
    // we're memory-bound).
    __shared__ double sdata[NTHREADS];
    sdata[threadIdx.x] = (double)acc0 + (double)acc1 + (double)acc2 + (double)acc3;
    __syncthreads();
    #pragma unroll
    for (int s = NTHREADS / 2; s >= 32; s >>= 1) {
        if (threadIdx.x < s) sdata[threadIdx.x] += sdata[threadIdx.x + s];
        __syncthreads();
    }

    __shared__ bool s_is_last;
    if (threadIdx.x < 32) {
        double v = sdata[threadIdx.x];
        #pragma unroll
        for (int off = 16; off > 0; off >>= 1)
            v += __shfl_down_sync(0xFFFFFFFFu, v, off);
        if (threadIdx.x == 0) {
            g_partials[blockIdx.x] = v;
            __threadfence();
            unsigned int my_ticket = atomicAdd(&g_ticket, 1u);
            s_is_last = (my_ticket == NBLOCKS - 1);
        }
    }
    __syncthreads();

    if (s_is_last) {
        // Last-arriving block: sum all partials in a FIXED order
        // (deterministic across replays), write result, reset ticket.
        double v = 0.0;
        for (int j = threadIdx.x; j < NBLOCKS; j += NTHREADS)
            v += g_partials[j];
        sdata[threadIdx.x] = v;
        __syncthreads();
        #pragma unroll
        for (int s = NTHREADS / 2; s >= 32; s >>= 1) {
            if (threadIdx.x < s) sdata[threadIdx.x] += sdata[threadIdx.x + s];
            __syncthreads();
        }
        if (threadIdx.x < 32) {
            double w = sdata[threadIdx.x];
            #pragma unroll
            for (int off = 16; off > 0; off >>= 1)
                w += __shfl_down_sync(0xFFFFFFFFu, w, off);
            if (threadIdx.x == 0) {
                out[0] = (float)(w * inv_n);
                g_ticket = 0;   // restore state for next graph replay
            }
        }
    }
}

extern "C" void kernel_launch(void* const* d_in, const int* in_sizes, int n_in,
                              void* d_out, int out_size) {
    const float* x = (const float*)d_in[0];
    const float* t = (const float*)d_in[1];
    float* out = (float*)d_out;

    int n = in_sizes[0];   // 12,582,912
    int n4 = n / 4;        // exactly divisible

    swt_mse_kernel<<<NBLOCKS, NTHREADS>>>(
        (const float4*)x, (const float4*)t, n4, out, 1.0 / (double)n);
}

// round 10
// speedup vs baseline: 1.2602x; 1.2602x over previous
#include <cuda_runtime.h>

// SWT Haar level-1 MSE loss reduces analytically to plain MSE:
//   loss = mean((x - target)^2)
// (with d = x - t: ((d[i]+d[i+1])^2 + (d[i+1]-d[i])^2)/2 = d[i]^2 + d[i+1]^2;
//  circular sum = 2*sum(d^2); mean over 2N coeffs = sum(d^2)/N.)
//
// N = 16*3*512*512 = 12,582,912 floats per input.
//
// oe=1 config: 152 blocks (GB300 has 152 SMs) x 1024 threads, one CTA per
// SM, to eliminate the cross-CTA L1tex-queue spread that capped the oe=8
// version at DRAM=45%. Streaming loads (__ldcs): data is touched exactly
// once, keep L2 clean.

#define NBLOCKS 152
#define NTHREADS 1024
#define UNROLL 4

__device__ double g_partials[NBLOCKS];
__device__ unsigned int g_ticket = 0;   // always 0 between launches

__global__ void __launch_bounds__(NTHREADS)
swt_mse_kernel(const float4* __restrict__ x,
               const float4* __restrict__ t,
               int n4, float* __restrict__ out, double inv_n) {
    const int tid    = blockIdx.x * NTHREADS + threadIdx.x;
    const int stride = NBLOCKS * NTHREADS;

    float acc0 = 0.0f, acc1 = 0.0f, acc2 = 0.0f, acc3 = 0.0f;

    // 8 independent streaming LDG.128 front-batched per trip (MLP_p1 = 8).
    int i = tid;
    const int bound = n4 - (UNROLL - 1) * stride;
    for (; i < bound; i += UNROLL * stride) {
        float4 a0 = __ldcs(&x[i]);
        float4 a1 = __ldcs(&x[i + stride]);
        float4 a2 = __ldcs(&x[i + 2 * stride]);
        float4 a3 = __ldcs(&x[i + 3 * stride]);
        float4 b0 = __ldcs(&t[i]);
        float4 b1 = __ldcs(&t[i + stride]);
        float4 b2 = __ldcs(&t[i + 2 * stride]);
        float4 b3 = __ldcs(&t[i + 3 * stride]);

        float d;
        d = a0.x - b0.x; acc0 += d * d;
        d = a0.y - b0.y; acc0 += d * d;
        d = a0.z - b0.z; acc0 += d * d;
        d = a0.w - b0.w; acc0 += d * d;
        d = a1.x - b1.x; acc1 += d * d;
        d = a1.y - b1.y; acc1 += d * d;
        d = a1.z - b1.z; acc1 += d * d;
        d = a1.w - b1.w; acc1 += d * d;
        d = a2.x - b2.x; acc2 += d * d;
        d = a2.y - b2.y; acc2 += d * d;
        d = a2.z - b2.z; acc2 += d * d;
        d = a2.w - b2.w; acc2 += d * d;
        d = a3.x - b3.x; acc3 += d * d;
        d = a3.y - b3.y; acc3 += d * d;
        d = a3.z - b3.z; acc3 += d * d;
        d = a3.w - b3.w; acc3 += d * d;
    }
    // Tail trips
    for (; i < n4; i += stride) {
        float4 a = __ldcs(&x[i]);
        float4 b = __ldcs(&t[i]);
        float d;
        d = a.x - b.x; acc0 += d * d;
        d = a.y - b.y; acc1 += d * d;
        d = a.z - b.z; acc2 += d * d;
        d = a.w - b.w; acc3 += d * d;
    }

    // Block reduction (promote to double; free — memory-bound kernel).
    __shared__ double sdata[NTHREADS];
    sdata[threadIdx.x] = (double)acc0 + (double)acc1 + (double)acc2 + (double)acc3;
    __syncthreads();
    #pragma unroll
    for (int s = NTHREADS / 2; s >= 32; s >>= 1) {
        if (threadIdx.x < s) sdata[threadIdx.x] += sdata[threadIdx.x + s];
        __syncthreads();
    }

    __shared__ bool s_is_last;
    if (threadIdx.x < 32) {
        double v = sdata[threadIdx.x];
        #pragma unroll
        for (int off = 16; off > 0; off >>= 1)
            v += __shfl_down_sync(0xFFFFFFFFu, v, off);
        if (threadIdx.x == 0) {
            g_partials[blockIdx.x] = v;
            __threadfence();
            unsigned int my_ticket = atomicAdd(&g_ticket, 1u);
            s_is_last = (my_ticket == NBLOCKS - 1);
        }
    }
    __syncthreads();

    if (s_is_last) {
        // Last block: fixed-order sum of 152 partials (deterministic),
        // write result, reset ticket for the next graph replay.
        double v = 0.0;
        for (int j = threadIdx.x; j < NBLOCKS; j += NTHREADS)
            v += g_partials[j];
        sdata[threadIdx.x] = v;
        __syncthreads();
        #pragma unroll
        for (int s = NTHREADS / 2; s >= 32; s >>= 1) {
            if (threadIdx.x < s) sdata[threadIdx.x] += sdata[threadIdx.x + s];
            __syncthreads();
        }
        if (threadIdx.x < 32) {
            double w = sdata[threadIdx.x];
            #pragma unroll
            for (int off = 16; off > 0; off >>= 1)
                w += __shfl_down_sync(0xFFFFFFFFu, w, off);
            if (threadIdx.x == 0) {
                out[0] = (float)(w * inv_n);
                g_ticket = 0;
            }
        }
    }
}

extern "C" void kernel_launch(void* const* d_in, const int* in_sizes, int n_in,
                              void* d_out, int out_size) {
    const float* x = (const float*)d_in[0];
    const float* t = (const float*)d_in[1];
    float* out = (float*)d_out;

    int n = in_sizes[0];   // 12,582,912
    int n4 = n / 4;

    swt_mse_kernel<<<NBLOCKS, NTHREADS>>>(
        (const float4*)x, (const float4*)t, n4, out, 1.0 / (double)n);
}